// round 7
// baseline (speedup 1.0000x reference)
#include <cuda_runtime.h>
#include <cstdint>

// out[b,t,a] = start_state[b,a] + (t/255) * patterns[iid[b], t, a]
// B=256, T=256, AD=64.
//
// R7: reads via per-thread cp.async.cg (LDGSTS, 16B each) -> smem.
//  - no register writeback, bypasses the L1tex wavefront completion queue
//  - no depth cap: 1024 cp.asyncs in flight per CTA (~114KB/SM outstanding)
//  - full SM coverage (grid 1024, ~7 CTAs/SM), unlike the R5 bulk version
// Stores use the proven warp STG.128 path.

#define B_   256
#define T_   256
#define AD_  64
#define TPB  256
#define CHUNK_T 64
#define CHUNK_F4 (CHUNK_T * 16)            // 1024 float4
#define CHUNK_BYTES (CHUNK_T * AD_ * 4)    // 16384

__global__ __launch_bounds__(TPB)
void traj_kernel(const float* __restrict__ start_state,    // [B, 64]
                 const int*   __restrict__ instruction_id, // [B]
                 const float* __restrict__ patterns,       // [V, T, 64]
                 float*       __restrict__ out)            // [B, T, 64]
{
    __shared__ alignas(128) float4 buf[CHUNK_F4];          // 16 KB

    const unsigned bid   = blockIdx.x;
    const unsigned b     = bid >> 2;
    const unsigned chunk = bid & 3u;
    const unsigned tid   = threadIdx.x;

    const int iid = __ldg(&instruction_id[b]);
    const float4* __restrict__ src =
        (const float4*)(patterns + ((size_t)iid * T_ + (size_t)chunk * CHUNK_T) * AD_);

    // 4 cp.async.cg per thread, issued back-to-back: 1024 in flight per CTA.
#pragma unroll
    for (int k = 0; k < 4; k++) {
        const unsigned j = tid + (unsigned)k * TPB;        // 0..1023
        const uint32_t dst_s = (uint32_t)__cvta_generic_to_shared(&buf[j]);
        asm volatile("cp.async.cg.shared.global [%0], [%1], 16;"
                     :: "r"(dst_s), "l"(src + j) : "memory");
    }
    asm volatile("cp.async.commit_group;" ::: "memory");

    // Overlap with the async copies: invariant per-thread state.
    // j = tid + k*256 -> a4 = j & 15 = tid & 15 for all k.
    const unsigned a4 = tid & 15u;
    const float4 s = __ldg((const float4*)(start_state + (size_t)b * AD_) + a4);

    asm volatile("cp.async.wait_group 0;" ::: "memory");
    __syncthreads();

    float4* __restrict__ dst =
        (float4*)(out + ((size_t)b * T_ + (size_t)chunk * CHUNK_T) * AD_);

#pragma unroll
    for (int k = 0; k < 4; k++) {
        const unsigned j  = tid + (unsigned)k * TPB;       // 0..1023
        const unsigned tl = j >> 4;                        // local t 0..63
        const float prog = (float)(chunk * CHUNK_T + tl) * (1.0f / (float)(T_ - 1));
        float4 p = buf[j];
        p.x = fmaf(prog, p.x, s.x);
        p.y = fmaf(prog, p.y, s.y);
        p.z = fmaf(prog, p.z, s.z);
        p.w = fmaf(prog, p.w, s.w);
        dst[j] = p;
    }
}

extern "C" void kernel_launch(void* const* d_in, const int* in_sizes, int n_in,
                              void* d_out, int out_size)
{
    const float* start_state    = (const float*)d_in[0];
    const int*   instruction_id = (const int*)  d_in[1];
    const float* patterns       = (const float*)d_in[27];
    float*       out            = (float*)d_out;

    traj_kernel<<<B_ * 4, TPB>>>(start_state, instruction_id, patterns, out);
}